// round 3
// baseline (speedup 1.0000x reference)
#include <cuda_runtime.h>
#include <cstdint>

// MVFModuleChannelsLast — B=8, T=40, H=32, W=32, C=64, C_MVF=32, K=3
// out[...,0:32] = relu(convT+convH+convW on x[...,0:32]); out[...,32:64] = skip
// 7 merged tap matrices (centers summed). t-rolling CTA with cp.async-staged
// swizzled smem planes; fully coalesced global traffic.

#define Bv 8
#define Tv 40
#define Hv 32
#define Wv 32

#define TC 10                       // t-steps per CTA
#define RR 8                        // h rows per CTA
#define PROWS (RR + 2)              // with h halo
#define PLANE_F4 (PROWS * 32 * 8)   // 2560 float4 = 40KB
#define WS_F4 1792                  // 7*32*32 floats = 28KB
#define STAGE_F4 (RR * 32 * 8)      // 2048 float4 = 32KB
#define SMEM_F4 (WS_F4 + 4 * PLANE_F4 + STAGE_F4)   // 14080
#define SMEM_BYTES (SMEM_F4 * 16)                   // 225280

__device__ __forceinline__ unsigned long long pack2(float a) {
    unsigned long long r;
    unsigned int ai = __float_as_uint(a);
    asm("mov.b64 %0, {%1, %1};" : "=l"(r) : "r"(ai));
    return r;
}
__device__ __forceinline__ unsigned long long mk2(float lo, float hi) {
    unsigned long long r;
    asm("mov.b64 %0, {%1, %2};" : "=l"(r) : "r"(__float_as_uint(lo)), "r"(__float_as_uint(hi)));
    return r;
}
__device__ __forceinline__ void fma2(unsigned long long &d, unsigned long long a, unsigned long long b) {
    asm("fma.rn.f32x2 %0, %1, %2, %0;" : "+l"(d) : "l"(a), "l"(b));
}
__device__ __forceinline__ void unpack2(unsigned long long v, float &lo, float &hi) {
    unsigned int l, h;
    asm("mov.b64 {%0, %1}, %2;" : "=r"(l), "=r"(h) : "l"(v));
    lo = __uint_as_float(l);
    hi = __uint_as_float(h);
}
__device__ __forceinline__ void cpa16(uint32_t dst, const void* src, int sz) {
    asm volatile("cp.async.cg.shared.global [%0], [%1], 16, %2;"
                 :: "r"(dst), "l"(src), "r"(sz));
}

// Issue one plane's cp.asyncs (tau = absolute t, may be out of range -> zfill).
// Stored swizzled: f4 index (r*32 + w)*8 + (c4 ^ (w&7)), r = 0..9 maps h0-1..h0+8.
__device__ __forceinline__ void issue_plane(const float4* __restrict__ x4,
                                            float4* planes, int b, int tau,
                                            int h0, int tid) {
    float4* dst = planes + ((tau + 4) & 3) * PLANE_F4;
    const bool vt = (tau >= 0) && (tau < Tv);
    const int tcl = vt ? tau : 0;
    const int tb = (b * Tv + tcl) * Hv;
    #pragma unroll
    for (int k = 0; k < 20; ++k) {
        int idx = tid + k * 128;            // 0..2559
        int r   = idx >> 8;                 // 0..9
        int rem = idx & 255;
        int wv  = rem >> 3;
        int c4  = rem & 7;
        int gh  = h0 - 1 + r;
        bool v  = vt && (gh >= 0) && (gh < Hv);
        int ghc = v ? gh : 0;
        const float4* src = x4 + ((tb + ghc) * Wv + wv) * 16 + c4;
        uint32_t d = (uint32_t)__cvta_generic_to_shared(
            dst + (r * 32 + wv) * 8 + (c4 ^ (wv & 7)));
        cpa16(d, src, v ? 16 : 0);
    }
    asm volatile("cp.async.commit_group;" ::: "memory");
}

__global__ __launch_bounds__(128, 1) void mvf_kernel(
    const float4* __restrict__ x4, const float* __restrict__ wT,
    const float* __restrict__ wH, const float* __restrict__ wW,
    float4* __restrict__ out4)
{
    extern __shared__ float4 smem[];
    float*  wsf    = (float*)smem;          // weights: 7*1024 floats
    float4* planes = smem + WS_F4;          // 4 plane slots
    float4* stg    = smem + WS_F4 + 4 * PLANE_F4;

    const int tx  = threadIdx.x;            // w
    const int ty  = threadIdx.y;            // h-pair
    const int tid = ty * 32 + tx;
    const int b   = blockIdx.x;
    const int h0  = blockIdx.y * RR;
    const int t0  = blockIdx.z * TC;

    // Weight prep: m0 merged centers; m1/m2 = wT k0/k2; m3/m4 = wH; m5/m6 = wW.
    for (int i = tid; i < 1024; i += 128) {
        wsf[i]        = wT[1024 + i] + wH[1024 + i] + wW[1024 + i];
        wsf[1024 + i] = wT[i];
        wsf[2048 + i] = wT[2048 + i];
        wsf[3072 + i] = wH[i];
        wsf[4096 + i] = wH[2048 + i];
        wsf[5120 + i] = wW[i];
        wsf[6144 + i] = wW[2048 + i];
    }

    // Prologue: planes t0-1, t0, t0+1 in flight.
    issue_plane(x4, planes, b, t0 - 1, h0, tid);
    issue_plane(x4, planes, b, t0,     h0, tid);
    issue_plane(x4, planes, b, t0 + 1, h0, tid);

    const int sr0 = 2 * ty + 1;             // stored center row of voxel r0

    for (int t = t0; t < t0 + TC; ++t) {
        issue_plane(x4, planes, b, t + 2, h0, tid);       // overlaps compute t
        asm volatile("cp.async.wait_group 1;" ::: "memory");  // t+1 resident
        __syncthreads();

        // ---- compute: 2 voxels/thread, rows (2ty, 2ty+1) at width tx ----
        const int sA = (t + 3) & 3;         // slot of plane t-1
        const int sB = t & 3;               // t
        const int sC = (t + 1) & 3;         // t+1

        unsigned long long acc0[16], acc1[16];
        #pragma unroll
        for (int j = 0; j < 16; ++j) { acc0[j] = 0ull; acc1[j] = 0ull; }

        #pragma unroll 1
        for (int m = 0; m < 7; ++m) {
            const int ps = (m == 1) ? sA : ((m == 2) ? sC : sB);
            const int dr = (m == 3) ? -1 : ((m == 4) ? 1 : 0);
            const int dw = (m == 5) ? -1 : ((m == 6) ? 1 : 0);
            int wv = tx + dw;
            float z = 1.f;
            if (wv < 0 || wv > 31) { wv = tx; z = 0.f; }
            const float4* P = planes + ps * PLANE_F4 + ((sr0 + dr) * 32 + wv) * 8;
            const int sw2 = wv & 7;
            const float4* wmat = smem + m * 256;

            #pragma unroll 2
            for (int c4 = 0; c4 < 8; ++c4) {
                float4 xq0 = P[(c4 ^ sw2)];
                float4 xq1 = P[256 + (c4 ^ sw2)];
                const float4* wrow = wmat + c4 * 32;
                #pragma unroll
                for (int s = 0; s < 4; ++s) {
                    float a0 = ((s == 0) ? xq0.x : (s == 1) ? xq0.y : (s == 2) ? xq0.z : xq0.w) * z;
                    float a1 = ((s == 0) ? xq1.x : (s == 1) ? xq1.y : (s == 2) ? xq1.z : xq1.w) * z;
                    unsigned long long xx0 = pack2(a0);
                    unsigned long long xx1 = pack2(a1);
                    const float4* wr = wrow + s * 8;
                    #pragma unroll
                    for (int jq = 0; jq < 8; ++jq) {
                        float4 wf = wr[jq];                 // broadcast LDS.128
                        unsigned long long wlo = mk2(wf.x, wf.y);
                        unsigned long long whi = mk2(wf.z, wf.w);
                        fma2(acc0[2 * jq],     xx0, wlo);
                        fma2(acc0[2 * jq + 1], xx0, whi);
                        fma2(acc1[2 * jq],     xx1, wlo);
                        fma2(acc1[2 * jq + 1], xx1, whi);
                    }
                }
            }
        }
        __syncthreads();                    // all reads of plane slots done

        // ---- stage relu results into swizzled stage buffer ----
        {
            const int base0 = ((2 * ty) * 32 + tx) * 8;
            const int sw = tx & 7;
            #pragma unroll
            for (int jq = 0; jq < 8; ++jq) {
                float a, bb, c, d;
                unpack2(acc0[2 * jq], a, bb);
                unpack2(acc0[2 * jq + 1], c, d);
                stg[base0 + (jq ^ sw)] =
                    make_float4(fmaxf(a, 0.f), fmaxf(bb, 0.f), fmaxf(c, 0.f), fmaxf(d, 0.f));
                unpack2(acc1[2 * jq], a, bb);
                unpack2(acc1[2 * jq + 1], c, d);
                stg[base0 + 256 + (jq ^ sw)] =
                    make_float4(fmaxf(a, 0.f), fmaxf(bb, 0.f), fmaxf(c, 0.f), fmaxf(d, 0.f));
            }
        }
        __syncthreads();

        // ---- cooperative coalesced store: conv out + skip copy ----
        {
            const int vb = ((b * Tv + t) * Hv + h0) * Wv * 16;  // f4 index of (t,h0,0)
            #pragma unroll
            for (int k = 0; k < 16; ++k) {
                int idx = tid + k * 128;        // 0..2047
                int vox = idx >> 3;             // 0..255
                int c4  = idx & 7;
                int wv  = vox & 31;
                int g   = vb + vox * 16;
                out4[g + c4]     = stg[vox * 8 + (c4 ^ (wv & 7))];
                out4[g + 8 + c4] = x4[g + 8 + c4];
            }
        }
        // no sync needed: next iteration's wait+syncthreads orders the
        // stage-buffer reuse and plane-slot overwrite.
    }
}

extern "C" void kernel_launch(void* const* d_in, const int* in_sizes, int n_in,
                              void* d_out, int out_size) {
    const float4* x4 = (const float4*)d_in[0];
    const float*  wT = (const float*)d_in[1];
    const float*  wH = (const float*)d_in[2];
    const float*  wW = (const float*)d_in[3];
    cudaFuncSetAttribute(mvf_kernel, cudaFuncAttributeMaxDynamicSharedMemorySize, SMEM_BYTES);
    dim3 grid(Bv, Hv / RR, Tv / TC);   // 8 x 4 x 4 = 128 CTAs, ~one wave
    dim3 block(32, 4);
    mvf_kernel<<<grid, block, SMEM_BYTES>>>(x4, wT, wH, wW, (float4*)d_out);
}

// round 6
// speedup vs baseline: 1.1227x; 1.1227x over previous
#include <cuda_runtime.h>
#include <cstdint>

// MVFModuleChannelsLast — B=8, T=40, H=32, W=32, C=64, C_MVF=32, K=3
// out[...,0:32] = relu(convT+convH+convW on x[...,0:32]); out[...,32:64] = skip
// 7 merged tap matrices (centers summed). t-rolling 4-plane cp.async ring
// (zfill gives SAME padding for t/h taps), 256 thr/CTA, 1 voxel/thread,
// packed f32x2 FMAs, lane-remapped fully-coalesced skip copy.

#define Bv 8
#define Tv 40
#define Hv 32
#define Wv 32

#define TC 10
#define RR 8
#define PROWS (RR + 2)
#define PLANE_F4 (PROWS * 32 * 8)  // 2560 float4 = 40KB per plane
#define WS_F4 1792                 // 7*32*32 floats = 28KB weights
#define SMEM_BYTES ((WS_F4 + 4 * PLANE_F4) * 16)   // 192512 B

__device__ __forceinline__ unsigned long long pack2(float a) {
    unsigned long long r;
    unsigned int ai = __float_as_uint(a);
    asm("mov.b64 %0, {%1, %1};" : "=l"(r) : "r"(ai));
    return r;
}
__device__ __forceinline__ void fma2(unsigned long long &d, unsigned long long a, unsigned long long b) {
    asm("fma.rn.f32x2 %0, %1, %2, %0;" : "+l"(d) : "l"(a), "l"(b));
}
__device__ __forceinline__ void unpack2(unsigned long long v, float &lo, float &hi) {
    unsigned int l, h;
    asm("mov.b64 {%0, %1}, %2;" : "=r"(l), "=r"(h) : "l"(v));
    lo = __uint_as_float(l);
    hi = __uint_as_float(h);
}
__device__ __forceinline__ void cpa16(uint32_t dst, const void* src, int sz) {
    asm volatile("cp.async.cg.shared.global [%0], [%1], 16, %2;"
                 :: "r"(dst), "l"(src), "r"(sz));
}

// Plane tau -> ring slot (tau+4)&3. Swizzle: f4 idx (r*32+w)*8 + (c4 ^ (w&7)).
// Out-of-range t/h rows zero-filled via cp.async src-size 0 (SAME padding).
__device__ __forceinline__ void issue_plane(const float4* __restrict__ x4,
                                            float4* planes, int b, int tau,
                                            int h0, int tid) {
    float4* dst = planes + ((tau + 4) & 3) * PLANE_F4;
    const bool vt = (tau >= 0) && (tau < Tv);
    const int tb = (b * Tv + (vt ? tau : 0)) * Hv;
    #pragma unroll
    for (int k = 0; k < 10; ++k) {
        int idx = tid + k * 256;            // 0..2559
        int r   = idx >> 8;                 // 0..9 -> rows h0-1 .. h0+8
        int rem = idx & 255;
        int wv  = rem >> 3;
        int c4  = rem & 7;
        int gh  = h0 - 1 + r;
        bool v  = vt && (gh >= 0) && (gh < Hv);
        const float4* src = x4 + ((tb + (v ? gh : 0)) * Wv + wv) * 16 + c4;
        uint32_t d = (uint32_t)__cvta_generic_to_shared(
            dst + (r * 32 + wv) * 8 + (c4 ^ (wv & 7)));
        cpa16(d, src, v ? 16 : 0);
    }
    asm volatile("cp.async.commit_group;" ::: "memory");
}

__global__ __launch_bounds__(256, 1) void mvf_kernel(
    const float4* __restrict__ x4, const float* __restrict__ wT,
    const float* __restrict__ wH, const float* __restrict__ wW,
    float4* __restrict__ out4)
{
    extern __shared__ float4 smem[];
    float*  wsf    = (float*)smem;          // weights
    float4* planes = smem + WS_F4;          // 4-slot ring

    const int tid = threadIdx.x;
    const int r   = tid >> 5;               // h row 0..7 (warp id)
    const int wv  = tid & 31;               // w (lane)
    const int b   = blockIdx.x;
    const int h0  = blockIdx.y * RR;
    const int t0  = blockIdx.z * TC;

    // m0 merged centers; m1/m2 = wT k0/k2; m3/m4 = wH; m5/m6 = wW.
    for (int i = tid; i < 1024; i += 256) {
        wsf[i]        = wT[1024 + i] + wH[1024 + i] + wW[1024 + i];
        wsf[1024 + i] = wT[i];
        wsf[2048 + i] = wT[2048 + i];
        wsf[3072 + i] = wH[i];
        wsf[4096 + i] = wH[2048 + i];
        wsf[5120 + i] = wW[i];
        wsf[6144 + i] = wW[2048 + i];
    }

    issue_plane(x4, planes, b, t0 - 1, h0, tid);
    issue_plane(x4, planes, b, t0,     h0, tid);
    issue_plane(x4, planes, b, t0 + 1, h0, tid);

    const int sr  = r + 1;
    // per-tap lane shift for the two w taps; invalid lanes read own voxel * 0
    const int wm5 = (wv > 0)  ? wv - 1 : wv;
    const int wm6 = (wv < 31) ? wv + 1 : wv;
    const float zm5 = (wv > 0)  ? 1.f : 0.f;
    const float zm6 = (wv < 31) ? 1.f : 0.f;

    for (int t = t0; t < t0 + TC; ++t) {
        issue_plane(x4, planes, b, t + 2, h0, tid);           // overlaps compute t
        asm volatile("cp.async.wait_group 1;" ::: "memory");  // t+1 resident
        __syncthreads();

        const int sA = (t + 3) & 3, sB = t & 3, sC = (t + 1) & 3;

        unsigned long long acc[16];   // acc[j] = co pair (2j, 2j+1)
        #pragma unroll
        for (int j = 0; j < 16; ++j) acc[j] = 0ull;

        #pragma unroll 1
        for (int m = 0; m < 7; ++m) {
            const int ps  = (m == 1) ? sA : ((m == 2) ? sC : sB);
            const int row = sr + ((m == 3) ? -1 : (m == 4) ? 1 : 0);
            const int wl  = (m == 5) ? wm5 : (m == 6) ? wm6 : wv;
            const float z = (m == 5) ? zm5 : (m == 6) ? zm6 : 1.f;
            const float4* P = planes + ps * PLANE_F4 + (row * 32 + wl) * 8;
            const int sw = wl & 7;
            const ulonglong2* wmat = (const ulonglong2*)(smem + m * 256);

            #pragma unroll 2
            for (int c4 = 0; c4 < 8; ++c4) {
                float4 xq = P[c4 ^ sw];
                const ulonglong2* wrow = wmat + c4 * 32;   // 4 ci rows, 8 u2/row
                #pragma unroll
                for (int s = 0; s < 4; ++s) {
                    float a = ((s == 0) ? xq.x : (s == 1) ? xq.y : (s == 2) ? xq.z : xq.w) * z;
                    unsigned long long xx = pack2(a);
                    const ulonglong2* wr = wrow + s * 8;   // this ci's 32 co
                    #pragma unroll
                    for (int jq = 0; jq < 8; ++jq) {
                        ulonglong2 wp = wr[jq];            // broadcast LDS.128
                        fma2(acc[2 * jq],     xx, wp.x);
                        fma2(acc[2 * jq + 1], xx, wp.y);
                    }
                }
            }
        }
        __syncthreads();   // plane reads done -> dead slot reusable next iter

        // direct conv store (this thread's voxel, lane-major = coalesced)
        const int rowb = ((b * Tv + t) * Hv + h0 + r) * Wv;
        float4* o = out4 + (long)(rowb + wv) * 16;
        #pragma unroll
        for (int q = 0; q < 8; ++q) {
            float a, bb, c, d;
            unpack2(acc[2 * q],     a, bb);
            unpack2(acc[2 * q + 1], c, d);
            o[q] = make_float4(fmaxf(a, 0.f), fmaxf(bb, 0.f), fmaxf(c, 0.f), fmaxf(d, 0.f));
        }

        // coalesced skip copy: lanes remapped to (voxel, c4)
        {
            const long base = (long)rowb * 16;
            const int lc4 = wv & 7;
            const int lv  = wv >> 3;
            #pragma unroll
            for (int it = 0; it < 8; ++it) {
                long g = base + (long)(it * 4 + lv) * 16 + 8 + lc4;
                out4[g] = __ldg(x4 + g);
            }
        }
    }
}

extern "C" void kernel_launch(void* const* d_in, const int* in_sizes, int n_in,
                              void* d_out, int out_size) {
    const float4* x4 = (const float4*)d_in[0];
    const float*  wT = (const float*)d_in[1];
    const float*  wH = (const float*)d_in[2];
    const float*  wW = (const float*)d_in[3];
    cudaFuncSetAttribute(mvf_kernel, cudaFuncAttributeMaxDynamicSharedMemorySize, SMEM_BYTES);
    dim3 grid(Bv, Hv / RR, Tv / TC);   // 8 x 4 x 4 = 128 CTAs
    mvf_kernel<<<grid, 256, SMEM_BYTES>>>(x4, wT, wH, wW, (float4*)d_out);
}

// round 7
// speedup vs baseline: 1.3643x; 1.2152x over previous
#include <cuda_runtime.h>
#include <cstdint>

// MVFModuleChannelsLast — B=8, T=40, H=32, W=32, C=64, C_MVF=32, K=3
// out[...,0:32] = relu(convT+convH+convW on x[...,0:32]); out[...,32:64] = skip
// 7 merged tap matrices. t-PAIRED compute: each thread produces outputs for
// (t, t+1) so every weight LDS feeds 4 fma2 (halves weight wavefronts — the
// R6-measured bottleneck). 4-plane cp.async ring (zfill = SAME pad), 256
// thr/CTA, packed f32x2 FMAs, coalesced stores + skip copy.

#define Bv 8
#define Tv 40
#define Hv 32
#define Wv 32

#define TC 10                      // t-steps per CTA -> 5 pairs
#define RR 8
#define PROWS (RR + 2)
#define PLANE_F4 (PROWS * 32 * 8)  // 2560 float4 = 40KB per plane
#define WS_F4 1792                 // 7*32*32 floats = 28KB weights
#define SMEM_BYTES ((WS_F4 + 4 * PLANE_F4) * 16)   // 192512 B

__device__ __forceinline__ unsigned long long pack2(float a) {
    unsigned long long r;
    unsigned int ai = __float_as_uint(a);
    asm("mov.b64 %0, {%1, %1};" : "=l"(r) : "r"(ai));
    return r;
}
__device__ __forceinline__ void fma2(unsigned long long &d, unsigned long long a, unsigned long long b) {
    asm("fma.rn.f32x2 %0, %1, %2, %0;" : "+l"(d) : "l"(a), "l"(b));
}
__device__ __forceinline__ void unpack2(unsigned long long v, float &lo, float &hi) {
    unsigned int l, h;
    asm("mov.b64 {%0, %1}, %2;" : "=r"(l), "=r"(h) : "l"(v));
    lo = __uint_as_float(l);
    hi = __uint_as_float(h);
}
__device__ __forceinline__ void cpa16(uint32_t dst, const void* src, int sz) {
    asm volatile("cp.async.cg.shared.global [%0], [%1], 16, %2;"
                 :: "r"(dst), "l"(src), "r"(sz));
}

// Plane tau -> ring slot (tau+4)&3. Swizzle: f4 idx (r*32+w)*8 + (c4 ^ (w&7)).
// Out-of-range t/h rows zero-filled via cp.async src-size 0 (SAME padding).
__device__ __forceinline__ void issue_plane(const float4* __restrict__ x4,
                                            float4* planes, int b, int tau,
                                            int h0, int tid) {
    float4* dst = planes + ((tau + 4) & 3) * PLANE_F4;
    const bool vt = (tau >= 0) && (tau < Tv);
    const int tb = (b * Tv + (vt ? tau : 0)) * Hv;
    #pragma unroll
    for (int k = 0; k < 10; ++k) {
        int idx = tid + k * 256;            // 0..2559
        int r   = idx >> 8;                 // 0..9 -> rows h0-1 .. h0+8
        int rem = idx & 255;
        int wv  = rem >> 3;
        int c4  = rem & 7;
        int gh  = h0 - 1 + r;
        bool v  = vt && (gh >= 0) && (gh < Hv);
        const float4* src = x4 + ((tb + (v ? gh : 0)) * Wv + wv) * 16 + c4;
        uint32_t d = (uint32_t)__cvta_generic_to_shared(
            dst + (r * 32 + wv) * 8 + (c4 ^ (wv & 7)));
        cpa16(d, src, v ? 16 : 0);
    }
    asm volatile("cp.async.commit_group;" ::: "memory");
}

__global__ __launch_bounds__(256, 1) void mvf_kernel(
    const float4* __restrict__ x4, const float* __restrict__ wT,
    const float* __restrict__ wH, const float* __restrict__ wW,
    float4* __restrict__ out4)
{
    extern __shared__ float4 smem[];
    float*  wsf    = (float*)smem;          // weights
    float4* planes = smem + WS_F4;          // 4-slot ring

    const int tid = threadIdx.x;
    const int r   = tid >> 5;               // h row 0..7 (warp id)
    const int wv  = tid & 31;               // w (lane)
    const int b   = blockIdx.x;
    const int h0  = blockIdx.y * RR;
    const int t0  = blockIdx.z * TC;

    // m0 merged centers; m1/m2 = wT k0/k2; m3/m4 = wH; m5/m6 = wW.
    for (int i = tid; i < 1024; i += 256) {
        wsf[i]        = wT[1024 + i] + wH[1024 + i] + wW[1024 + i];
        wsf[1024 + i] = wT[i];
        wsf[2048 + i] = wT[2048 + i];
        wsf[3072 + i] = wH[i];
        wsf[4096 + i] = wH[2048 + i];
        wsf[5120 + i] = wW[i];
        wsf[6144 + i] = wW[2048 + i];
    }

    // Prologue: all 4 planes for the first pair (t0-1 .. t0+2).
    issue_plane(x4, planes, b, t0 - 1, h0, tid);
    issue_plane(x4, planes, b, t0,     h0, tid);
    issue_plane(x4, planes, b, t0 + 1, h0, tid);
    issue_plane(x4, planes, b, t0 + 2, h0, tid);

    const int sr  = r + 1;
    const int wm5 = (wv > 0)  ? wv - 1 : wv;
    const int wm6 = (wv < 31) ? wv + 1 : wv;
    const float zm5 = (wv > 0)  ? 1.f : 0.f;
    const float zm6 = (wv < 31) ? 1.f : 0.f;

    #pragma unroll 1
    for (int p = 0; p < TC / 2; ++p) {
        const int t = t0 + 2 * p;           // outputs t and t+1 this iteration
        asm volatile("cp.async.wait_group 0;" ::: "memory");
        __syncthreads();

        unsigned long long acc0[16], acc1[16];   // acc[j] = co pair (2j,2j+1)
        #pragma unroll
        for (int j = 0; j < 16; ++j) { acc0[j] = 0ull; acc1[j] = 0ull; }

        #pragma unroll 1
        for (int m = 0; m < 7; ++m) {
            const int dt  = (m == 1) ? -1 : (m == 2) ? 1 : 0;
            const int psA = (t + dt + 4) & 3;       // plane for output t
            const int psB = (t + 1 + dt + 4) & 3;   // plane for output t+1
            const int row = sr + ((m == 3) ? -1 : (m == 4) ? 1 : 0);
            const int wl  = (m == 5) ? wm5 : (m == 6) ? wm6 : wv;
            const float z = (m == 5) ? zm5 : (m == 6) ? zm6 : 1.f;
            const int po  = (row * 32 + wl) * 8;
            const float4* PA = planes + psA * PLANE_F4 + po;
            const float4* PB = planes + psB * PLANE_F4 + po;
            const int sw = wl & 7;
            const ulonglong2* wmat = (const ulonglong2*)(smem + m * 256);

            #pragma unroll 2
            for (int c4 = 0; c4 < 8; ++c4) {
                float4 xqA = PA[c4 ^ sw];
                float4 xqB = PB[c4 ^ sw];
                const ulonglong2* wrow = wmat + c4 * 32;  // 4 ci rows, 8 u2/row
                #pragma unroll
                for (int s = 0; s < 4; ++s) {
                    float aA = ((s == 0) ? xqA.x : (s == 1) ? xqA.y : (s == 2) ? xqA.z : xqA.w) * z;
                    float aB = ((s == 0) ? xqB.x : (s == 1) ? xqB.y : (s == 2) ? xqB.z : xqB.w) * z;
                    unsigned long long xxA = pack2(aA);
                    unsigned long long xxB = pack2(aB);
                    const ulonglong2* wr = wrow + s * 8;  // this ci's 32 co
                    #pragma unroll
                    for (int jq = 0; jq < 8; ++jq) {
                        ulonglong2 wp = wr[jq];           // 1 weight load -> 4 fma2
                        fma2(acc0[2 * jq],     xxA, wp.x);
                        fma2(acc0[2 * jq + 1], xxA, wp.y);
                        fma2(acc1[2 * jq],     xxB, wp.x);
                        fma2(acc1[2 * jq + 1], xxB, wp.y);
                    }
                }
            }
        }
        __syncthreads();   // plane reads done -> retired slots reusable

        // Prefetch next pair's two new planes (overwrite slots t-1, t).
        if (p < TC / 2 - 1) {
            issue_plane(x4, planes, b, t + 3, h0, tid);
            issue_plane(x4, planes, b, t + 4, h0, tid);
        }

        // Stores for both outputs (lane-major float4 = coalesced).
        const int rowbA = ((b * Tv + t) * Hv + h0 + r) * Wv;
        const int rowbB = rowbA + Hv * Wv;
        {
            float4* oA = out4 + (long)(rowbA + wv) * 16;
            float4* oB = out4 + (long)(rowbB + wv) * 16;
            #pragma unroll
            for (int q = 0; q < 8; ++q) {
                float a, bb, c, d;
                unpack2(acc0[2 * q], a, bb);
                unpack2(acc0[2 * q + 1], c, d);
                oA[q] = make_float4(fmaxf(a, 0.f), fmaxf(bb, 0.f), fmaxf(c, 0.f), fmaxf(d, 0.f));
                unpack2(acc1[2 * q], a, bb);
                unpack2(acc1[2 * q + 1], c, d);
                oB[q] = make_float4(fmaxf(a, 0.f), fmaxf(bb, 0.f), fmaxf(c, 0.f), fmaxf(d, 0.f));
            }
        }
        // Coalesced skip copy for both t's: lanes remapped to (voxel, c4).
        {
            const int lc4 = wv & 7;
            const int lv  = wv >> 3;
            const long baseA = (long)rowbA * 16;
            const long baseB = (long)rowbB * 16;
            #pragma unroll
            for (int it = 0; it < 8; ++it) {
                long gA = baseA + (long)(it * 4 + lv) * 16 + 8 + lc4;
                long gB = baseB + (long)(it * 4 + lv) * 16 + 8 + lc4;
                out4[gA] = __ldg(x4 + gA);
                out4[gB] = __ldg(x4 + gB);
            }
        }
    }
}

extern "C" void kernel_launch(void* const* d_in, const int* in_sizes, int n_in,
                              void* d_out, int out_size) {
    const float4* x4 = (const float4*)d_in[0];
    const float*  wT = (const float*)d_in[1];
    const float*  wH = (const float*)d_in[2];
    const float*  wW = (const float*)d_in[3];
    cudaFuncSetAttribute(mvf_kernel, cudaFuncAttributeMaxDynamicSharedMemorySize, SMEM_BYTES);
    dim3 grid(Bv, Hv / RR, Tv / TC);   // 8 x 4 x 4 = 128 CTAs
    mvf_kernel<<<grid, 256, SMEM_BYTES>>>(x4, wT, wH, wW, (float4*)d_out);
}

// round 8
// speedup vs baseline: 1.3815x; 1.0126x over previous
#include <cuda_runtime.h>
#include <cstdint>

// MVFModuleChannelsLast — B=8, T=40, H=32, W=32, C=64, C_MVF=32, K=3
// out[...,0:32] = relu(convT+convH+convW on x[...,0:32]); out[...,32:64] = skip
// 7 merged tap matrices. t-PAIRED compute + co-SPLIT warps: 512 thr/CTA,
// warps 0-7 -> co 0..15, warps 8-15 -> co 16..31 (same voxels). 4 warps/SMSP
// hides LDS latency; per-thread state halved. 4-plane cp.async ring
// (zfill = SAME pad), packed f32x2 FMAs, coalesced stores + skip copy.

#define Bv 8
#define Tv 40
#define Hv 32
#define Wv 32

#define TC 10                      // t-steps per CTA -> 5 pairs
#define RR 8
#define PROWS (RR + 2)
#define PLANE_F4 (PROWS * 32 * 8)  // 2560 float4 = 40KB per plane
#define WS_F4 1792                 // 7*32*32 floats = 28KB weights
#define SMEM_BYTES ((WS_F4 + 4 * PLANE_F4) * 16)   // 192512 B

#define NT 512

__device__ __forceinline__ unsigned long long pack2(float a) {
    unsigned long long r;
    unsigned int ai = __float_as_uint(a);
    asm("mov.b64 %0, {%1, %1};" : "=l"(r) : "r"(ai));
    return r;
}
__device__ __forceinline__ void fma2(unsigned long long &d, unsigned long long a, unsigned long long b) {
    asm("fma.rn.f32x2 %0, %1, %2, %0;" : "+l"(d) : "l"(a), "l"(b));
}
__device__ __forceinline__ void unpack2(unsigned long long v, float &lo, float &hi) {
    unsigned int l, h;
    asm("mov.b64 {%0, %1}, %2;" : "=r"(l), "=r"(h) : "l"(v));
    lo = __uint_as_float(l);
    hi = __uint_as_float(h);
}
__device__ __forceinline__ void cpa16(uint32_t dst, const void* src, int sz) {
    asm volatile("cp.async.cg.shared.global [%0], [%1], 16, %2;"
                 :: "r"(dst), "l"(src), "r"(sz));
}

// Plane tau -> ring slot (tau+4)&3. Swizzle: f4 idx (r*32+w)*8 + (c4 ^ (w&7)).
// Out-of-range t/h rows zero-filled via cp.async src-size 0 (SAME padding).
__device__ __forceinline__ void issue_plane(const float4* __restrict__ x4,
                                            float4* planes, int b, int tau,
                                            int h0, int tid) {
    float4* dst = planes + ((tau + 4) & 3) * PLANE_F4;
    const bool vt = (tau >= 0) && (tau < Tv);
    const int tb = (b * Tv + (vt ? tau : 0)) * Hv;
    #pragma unroll
    for (int k = 0; k < 5; ++k) {
        int idx = tid + k * NT;             // 0..2559
        int r   = idx >> 8;                 // 0..9 -> rows h0-1 .. h0+8
        int rem = idx & 255;
        int wv  = rem >> 3;
        int c4  = rem & 7;
        int gh  = h0 - 1 + r;
        bool v  = vt && (gh >= 0) && (gh < Hv);
        const float4* src = x4 + ((tb + (v ? gh : 0)) * Wv + wv) * 16 + c4;
        uint32_t d = (uint32_t)__cvta_generic_to_shared(
            dst + (r * 32 + wv) * 8 + (c4 ^ (wv & 7)));
        cpa16(d, src, v ? 16 : 0);
    }
    asm volatile("cp.async.commit_group;" ::: "memory");
}

__global__ __launch_bounds__(NT, 1) void mvf_kernel(
    const float4* __restrict__ x4, const float* __restrict__ wT,
    const float* __restrict__ wH, const float* __restrict__ wW,
    float4* __restrict__ out4)
{
    extern __shared__ float4 smem[];
    float*  wsf    = (float*)smem;          // weights
    float4* planes = smem + WS_F4;          // 4-slot ring

    const int tid  = threadIdx.x;
    const int wv   = tid & 31;              // w (lane)
    const int r    = (tid >> 5) & 7;        // h row 0..7
    const int half = tid >> 8;              // co half: 0 -> co 0..15, 1 -> 16..31
    const int b    = blockIdx.x;
    const int h0   = blockIdx.y * RR;
    const int t0   = blockIdx.z * TC;

    // m0 merged centers; m1/m2 = wT k0/k2; m3/m4 = wH; m5/m6 = wW.
    for (int i = tid; i < 1024; i += NT) {
        wsf[i]        = wT[1024 + i] + wH[1024 + i] + wW[1024 + i];
        wsf[1024 + i] = wT[i];
        wsf[2048 + i] = wT[2048 + i];
        wsf[3072 + i] = wH[i];
        wsf[4096 + i] = wH[2048 + i];
        wsf[5120 + i] = wW[i];
        wsf[6144 + i] = wW[2048 + i];
    }

    // Prologue: all 4 planes for the first pair (t0-1 .. t0+2).
    issue_plane(x4, planes, b, t0 - 1, h0, tid);
    issue_plane(x4, planes, b, t0,     h0, tid);
    issue_plane(x4, planes, b, t0 + 1, h0, tid);
    issue_plane(x4, planes, b, t0 + 2, h0, tid);

    const int sr  = r + 1;
    const int wm5 = (wv > 0)  ? wv - 1 : wv;
    const int wm6 = (wv < 31) ? wv + 1 : wv;
    const float zm5 = (wv > 0)  ? 1.f : 0.f;
    const float zm6 = (wv < 31) ? 1.f : 0.f;

    #pragma unroll 1
    for (int p = 0; p < TC / 2; ++p) {
        const int t = t0 + 2 * p;           // outputs t and t+1 this iteration
        asm volatile("cp.async.wait_group 0;" ::: "memory");
        __syncthreads();

        // acc[j] = co pair (half*16 + 2j, half*16 + 2j + 1)
        unsigned long long acc0[8], acc1[8];
        #pragma unroll
        for (int j = 0; j < 8; ++j) { acc0[j] = 0ull; acc1[j] = 0ull; }

        #pragma unroll 1
        for (int m = 0; m < 7; ++m) {
            const int dt  = (m == 1) ? -1 : (m == 2) ? 1 : 0;
            const int psA = (t + dt + 4) & 3;       // plane for output t
            const int psB = (t + 1 + dt + 4) & 3;   // plane for output t+1
            const int row = sr + ((m == 3) ? -1 : (m == 4) ? 1 : 0);
            const int wl  = (m == 5) ? wm5 : (m == 6) ? wm6 : wv;
            const float z = (m == 5) ? zm5 : (m == 6) ? zm6 : 1.f;
            const int po  = (row * 32 + wl) * 8;
            const float4* PA = planes + psA * PLANE_F4 + po;
            const float4* PB = planes + psB * PLANE_F4 + po;
            const int sw = wl & 7;
            const ulonglong2* wmat = (const ulonglong2*)(smem + m * 256);

            #pragma unroll 2
            for (int c4 = 0; c4 < 8; ++c4) {
                float4 xqA = PA[c4 ^ sw];
                float4 xqB = PB[c4 ^ sw];
                const ulonglong2* wrow = wmat + c4 * 32 + half * 4;  // this half's 16 co
                #pragma unroll
                for (int s = 0; s < 4; ++s) {
                    float aA = ((s == 0) ? xqA.x : (s == 1) ? xqA.y : (s == 2) ? xqA.z : xqA.w) * z;
                    float aB = ((s == 0) ? xqB.x : (s == 1) ? xqB.y : (s == 2) ? xqB.z : xqB.w) * z;
                    unsigned long long xxA = pack2(aA);
                    unsigned long long xxB = pack2(aB);
                    const ulonglong2* wr = wrow + s * 8;   // ci row, our half
                    #pragma unroll
                    for (int jq = 0; jq < 4; ++jq) {
                        ulonglong2 wp = wr[jq];            // 1 weight load -> 4 fma2
                        fma2(acc0[2 * jq],     xxA, wp.x);
                        fma2(acc0[2 * jq + 1], xxA, wp.y);
                        fma2(acc1[2 * jq],     xxB, wp.x);
                        fma2(acc1[2 * jq + 1], xxB, wp.y);
                    }
                }
            }
        }
        __syncthreads();   // plane reads done -> retired slots reusable

        // Prefetch next pair's two new planes (overwrite slots t-1, t).
        if (p < TC / 2 - 1) {
            issue_plane(x4, planes, b, t + 3, h0, tid);
            issue_plane(x4, planes, b, t + 4, h0, tid);
        }

        // Stores: this thread writes its co-half (4 float4 per t), coalesced.
        const int rowbA = ((b * Tv + t) * Hv + h0 + r) * Wv;
        const int rowbB = rowbA + Hv * Wv;
        {
            float4* oA = out4 + (long)(rowbA + wv) * 16 + half * 4;
            float4* oB = out4 + (long)(rowbB + wv) * 16 + half * 4;
            #pragma unroll
            for (int q = 0; q < 4; ++q) {
                float a, bb, c, d;
                unpack2(acc0[2 * q],     a, bb);
                unpack2(acc0[2 * q + 1], c, d);
                oA[q] = make_float4(fmaxf(a, 0.f), fmaxf(bb, 0.f), fmaxf(c, 0.f), fmaxf(d, 0.f));
                unpack2(acc1[2 * q],     a, bb);
                unpack2(acc1[2 * q + 1], c, d);
                oB[q] = make_float4(fmaxf(a, 0.f), fmaxf(bb, 0.f), fmaxf(c, 0.f), fmaxf(d, 0.f));
            }
        }
        // Coalesced skip copy for both t's (512 threads cover 2048 f4 per t).
        {
            const int lc4 = tid & 7;
            const int lv  = (tid >> 3) & 63;        // voxel group 0..63
            const long baseA = (long)rowbA - (long)r * Wv;  // (t, h0, 0) voxel idx
            const long baseB = baseA + Hv * Wv;
            #pragma unroll
            for (int it = 0; it < 4; ++it) {
                long voxo = (long)(it * 64 + lv) * 16 + 8 + lc4;
                long gA = baseA * 16 + voxo;
                long gB = baseB * 16 + voxo;
                out4[gA] = __ldg(x4 + gA);
                out4[gB] = __ldg(x4 + gB);
            }
        }
    }
}

extern "C" void kernel_launch(void* const* d_in, const int* in_sizes, int n_in,
                              void* d_out, int out_size) {
    const float4* x4 = (const float4*)d_in[0];
    const float*  wT = (const float*)d_in[1];
    const float*  wH = (const float*)d_in[2];
    const float*  wW = (const float*)d_in[3];
    cudaFuncSetAttribute(mvf_kernel, cudaFuncAttributeMaxDynamicSharedMemorySize, SMEM_BYTES);
    dim3 grid(Bv, Hv / RR, Tv / TC);   // 8 x 4 x 4 = 128 CTAs
    mvf_kernel<<<grid, NT, SMEM_BYTES>>>(x4, wT, wH, wW, (float4*)d_out);
}

// round 10
// speedup vs baseline: 1.3851x; 1.0026x over previous
#include <cuda_runtime.h>
#include <cstdint>

// MVFModuleChannelsLast — B=8, T=40, H=32, W=32, C=64, C_MVF=32, K=3
// out[...,0:32] = relu(convT+convH+convW on x[...,0:32]); out[...,32:64] = skip
// 7 merged tap matrices. V=4 compute (t-pair x h-pair) with co split 4 ways:
// each weight LDS.128 feeds 16 fma2, halving weight wavefronts (R8 bottleneck:
// L1 wf demand > fma floor). 4-plane cp.async ring (zfill = SAME pad).

#define Bv 8
#define Tv 40
#define Hv 32
#define Wv 32

#define TC 10                      // t-steps per CTA -> 5 pair-iterations
#define RR 8
#define PROWS (RR + 2)
#define PLANE_F4 (PROWS * 32 * 8)  // 2560 float4 = 40KB per plane
#define WS_F4 1792                 // 7*32*32 floats = 28KB weights
#define SMEM_BYTES ((WS_F4 + 4 * PLANE_F4) * 16)   // 192512 B

#define NT 512

__device__ __forceinline__ unsigned long long pack2(float a) {
    unsigned long long r;
    unsigned int ai = __float_as_uint(a);
    asm("mov.b64 %0, {%1, %1};" : "=l"(r) : "r"(ai));
    return r;
}
__device__ __forceinline__ void fma2(unsigned long long &d, unsigned long long a, unsigned long long b) {
    asm("fma.rn.f32x2 %0, %1, %2, %0;" : "+l"(d) : "l"(a), "l"(b));
}
__device__ __forceinline__ void unpack2(unsigned long long v, float &lo, float &hi) {
    unsigned int l, h;
    asm("mov.b64 {%0, %1}, %2;" : "=r"(l), "=r"(h) : "l"(v));
    lo = __uint_as_float(l);
    hi = __uint_as_float(h);
}
__device__ __forceinline__ void cpa16(uint32_t dst, const void* src, int sz) {
    asm volatile("cp.async.cg.shared.global [%0], [%1], 16, %2;"
                 :: "r"(dst), "l"(src), "r"(sz));
}

// Plane tau -> ring slot (tau+4)&3. Swizzle: f4 idx (r*32+w)*8 + (c4 ^ (w&7)).
// Out-of-range t/h rows zero-filled via cp.async src-size 0 (SAME padding).
__device__ __forceinline__ void issue_plane(const float4* __restrict__ x4,
                                            float4* planes, int b, int tau,
                                            int h0, int tid) {
    float4* dst = planes + ((tau + 4) & 3) * PLANE_F4;
    const bool vt = (tau >= 0) && (tau < Tv);
    const int tb = (b * Tv + (vt ? tau : 0)) * Hv;
    #pragma unroll
    for (int k = 0; k < 5; ++k) {
        int idx = tid + k * NT;             // 0..2559
        int r   = idx >> 8;                 // 0..9 -> rows h0-1 .. h0+8
        int rem = idx & 255;
        int wv  = rem >> 3;
        int c4  = rem & 7;
        int gh  = h0 - 1 + r;
        bool v  = vt && (gh >= 0) && (gh < Hv);
        const float4* src = x4 + ((tb + (v ? gh : 0)) * Wv + wv) * 16 + c4;
        uint32_t d = (uint32_t)__cvta_generic_to_shared(
            dst + (r * 32 + wv) * 8 + (c4 ^ (wv & 7)));
        cpa16(d, src, v ? 16 : 0);
    }
    asm volatile("cp.async.commit_group;" ::: "memory");
}

__global__ __launch_bounds__(NT, 1) void mvf_kernel(
    const float4* __restrict__ x4, const float* __restrict__ wT,
    const float* __restrict__ wH, const float* __restrict__ wW,
    float4* __restrict__ out4)
{
    extern __shared__ float4 smem[];
    float*  wsf    = (float*)smem;          // weights
    float4* planes = smem + WS_F4;          // 4-slot ring

    const int tid = threadIdx.x;
    const int wv  = tid & 31;               // w (lane)
    const int rp  = (tid >> 5) & 3;         // h row-pair: rows 2rp, 2rp+1
    const int q   = tid >> 7;               // co quarter: co 8q .. 8q+7
    const int b   = blockIdx.x;
    const int h0  = blockIdx.y * RR;
    const int t0  = blockIdx.z * TC;

    // m0 merged centers; m1/m2 = wT k0/k2; m3/m4 = wH; m5/m6 = wW.
    for (int i = tid; i < 1024; i += NT) {
        wsf[i]        = wT[1024 + i] + wH[1024 + i] + wW[1024 + i];
        wsf[1024 + i] = wT[i];
        wsf[2048 + i] = wT[2048 + i];
        wsf[3072 + i] = wH[i];
        wsf[4096 + i] = wH[2048 + i];
        wsf[5120 + i] = wW[i];
        wsf[6144 + i] = wW[2048 + i];
    }

    // Prologue: all 4 planes for the first pair (t0-1 .. t0+2).
    issue_plane(x4, planes, b, t0 - 1, h0, tid);
    issue_plane(x4, planes, b, t0,     h0, tid);
    issue_plane(x4, planes, b, t0 + 1, h0, tid);
    issue_plane(x4, planes, b, t0 + 2, h0, tid);

    const int sr0 = 2 * rp + 1;             // stored plane rows of the h-pair
    const int sr1 = 2 * rp + 2;
    const int wm5 = (wv > 0)  ? wv - 1 : wv;
    const int wm6 = (wv < 31) ? wv + 1 : wv;
    const float zm5 = (wv > 0)  ? 1.f : 0.f;
    const float zm6 = (wv < 31) ? 1.f : 0.f;

    #pragma unroll 1
    for (int p = 0; p < TC / 2; ++p) {
        const int t = t0 + 2 * p;           // outputs t and t+1 this iteration
        asm volatile("cp.async.wait_group 0;" ::: "memory");
        __syncthreads();

        // acc_v[j]: voxel v in {(t,r0),(t,r1),(t+1,r0),(t+1,r1)},
        // j = co pair (8q + 2j, 8q + 2j + 1)
        unsigned long long acc0[4], acc1[4], acc2[4], acc3[4];
        #pragma unroll
        for (int j = 0; j < 4; ++j) { acc0[j] = acc1[j] = acc2[j] = acc3[j] = 0ull; }

        #pragma unroll 1
        for (int m = 0; m < 7; ++m) {
            const int dt  = (m == 1) ? -1 : (m == 2) ? 1 : 0;
            const int psA = (t + dt + 4) & 3;       // plane for outputs at t
            const int psB = (t + 1 + dt + 4) & 3;   // plane for outputs at t+1
            const int dr  = (m == 3) ? -1 : (m == 4) ? 1 : 0;
            const int wl  = (m == 5) ? wm5 : (m == 6) ? wm6 : wv;
            const float z = (m == 5) ? zm5 : (m == 6) ? zm6 : 1.f;
            const int po0 = ((sr0 + dr) * 32 + wl) * 8;
            const int po1 = ((sr1 + dr) * 32 + wl) * 8;
            const float4* PA0 = planes + psA * PLANE_F4 + po0;
            const float4* PA1 = planes + psA * PLANE_F4 + po1;
            const float4* PB0 = planes + psB * PLANE_F4 + po0;
            const float4* PB1 = planes + psB * PLANE_F4 + po1;
            const int sw = wl & 7;
            // this quarter's weights: u2 index ci*8 + q*2 + jq
            const ulonglong2* wq = (const ulonglong2*)(smem + m * 256) + q * 2;

            #pragma unroll 2
            for (int c4 = 0; c4 < 8; ++c4) {
                const int xo = c4 ^ sw;
                float4 x0 = PA0[xo];
                float4 x1 = PA1[xo];
                float4 x2 = PB0[xo];
                float4 x3 = PB1[xo];
                const ulonglong2* wr = wq + c4 * 32;   // ci = c4*4 + s, stride 8 u2/ci
                #pragma unroll
                for (int s = 0; s < 4; ++s) {
                    float a0 = ((s == 0) ? x0.x : (s == 1) ? x0.y : (s == 2) ? x0.z : x0.w) * z;
                    float a1 = ((s == 0) ? x1.x : (s == 1) ? x1.y : (s == 2) ? x1.z : x1.w) * z;
                    float a2 = ((s == 0) ? x2.x : (s == 1) ? x2.y : (s == 2) ? x2.z : x2.w) * z;
                    float a3 = ((s == 0) ? x3.x : (s == 1) ? x3.y : (s == 2) ? x3.z : x3.w) * z;
                    unsigned long long xx0 = pack2(a0);
                    unsigned long long xx1 = pack2(a1);
                    unsigned long long xx2 = pack2(a2);
                    unsigned long long xx3 = pack2(a3);
                    ulonglong2 wpa = wr[s * 8];         // co 8q..8q+3
                    ulonglong2 wpb = wr[s * 8 + 1];     // co 8q+4..8q+7
                    fma2(acc0[0], xx0, wpa.x); fma2(acc0[1], xx0, wpa.y);
                    fma2(acc0[2], xx0, wpb.x); fma2(acc0[3], xx0, wpb.y);
                    fma2(acc1[0], xx1, wpa.x); fma2(acc1[1], xx1, wpa.y);
                    fma2(acc1[2], xx1, wpb.x); fma2(acc1[3], xx1, wpb.y);
                    fma2(acc2[0], xx2, wpa.x); fma2(acc2[1], xx2, wpa.y);
                    fma2(acc2[2], xx2, wpb.x); fma2(acc2[3], xx2, wpb.y);
                    fma2(acc3[0], xx3, wpa.x); fma2(acc3[1], xx3, wpa.y);
                    fma2(acc3[2], xx3, wpb.x); fma2(acc3[3], xx3, wpb.y);
                }
            }
        }
        __syncthreads();   // plane reads done -> retired slots reusable

        // Prefetch next pair's two new planes (overwrite slots t-1, t).
        if (p < TC / 2 - 1) {
            issue_plane(x4, planes, b, t + 3, h0, tid);
            issue_plane(x4, planes, b, t + 4, h0, tid);
        }

        // Stores: each thread writes 4 voxels x its co quarter (2 float4 each).
        const int rowbA = ((b * Tv + t) * Hv + h0 + 2 * rp) * Wv;   // (t, r0)
        {
            float4* o0 = out4 + (long)(rowbA + wv) * 16 + q * 2;             // (t,   r0)
            float4* o1 = out4 + (long)(rowbA + Wv + wv) * 16 + q * 2;        // (t,   r1)
            float4* o2 = out4 + (long)(rowbA + Hv * Wv + wv) * 16 + q * 2;   // (t+1, r0)
            float4* o3 = out4 + (long)(rowbA + Hv * Wv + Wv + wv) * 16 + q * 2;
            float a, bb, c, d;
            unpack2(acc0[0], a, bb); unpack2(acc0[1], c, d);
            o0[0] = make_float4(fmaxf(a,0.f), fmaxf(bb,0.f), fmaxf(c,0.f), fmaxf(d,0.f));
            unpack2(acc0[2], a, bb); unpack2(acc0[3], c, d);
            o0[1] = make_float4(fmaxf(a,0.f), fmaxf(bb,0.f), fmaxf(c,0.f), fmaxf(d,0.f));
            unpack2(acc1[0], a, bb); unpack2(acc1[1], c, d);
            o1[0] = make_float4(fmaxf(a,0.f), fmaxf(bb,0.f), fmaxf(c,0.f), fmaxf(d,0.f));
            unpack2(acc1[2], a, bb); unpack2(acc1[3], c, d);
            o1[1] = make_float4(fmaxf(a,0.f), fmaxf(bb,0.f), fmaxf(c,0.f), fmaxf(d,0.f));
            unpack2(acc2[0], a, bb); unpack2(acc2[1], c, d);
            o2[0] = make_float4(fmaxf(a,0.f), fmaxf(bb,0.f), fmaxf(c,0.f), fmaxf(d,0.f));
            unpack2(acc2[2], a, bb); unpack2(acc2[3], c, d);
            o2[1] = make_float4(fmaxf(a,0.f), fmaxf(bb,0.f), fmaxf(c,0.f), fmaxf(d,0.f));
            unpack2(acc3[0], a, bb); unpack2(acc3[1], c, d);
            o3[0] = make_float4(fmaxf(a,0.f), fmaxf(bb,0.f), fmaxf(c,0.f), fmaxf(d,0.f));
            unpack2(acc3[2], a, bb); unpack2(acc3[3], c, d);
            o3[1] = make_float4(fmaxf(a,0.f), fmaxf(bb,0.f), fmaxf(c,0.f), fmaxf(d,0.f));
        }
        // Coalesced skip copy for both t's (512 threads cover 2048 f4 per t).
        {
            const int lc4 = tid & 7;
            const int lv  = (tid >> 3) & 63;        // voxel group 0..63
            const long baseA = (long)((b * Tv + t) * Hv + h0) * Wv;  // (t, h0, 0)
            const long baseB = baseA + Hv * Wv;
            #pragma unroll
            for (int it = 0; it < 4; ++it) {
                long voxo = (long)(it * 64 + lv) * 16 + 8 + lc4;
                long gA = baseA * 16 + voxo;
                long gB = baseB * 16 + voxo;
                out4[gA] = __ldg(x4 + gA);
                out4[gB] = __ldg(x4 + gB);
            }
        }
    }
}

extern "C" void kernel_launch(void* const* d_in, const int* in_sizes, int n_in,
                              void* d_out, int out_size) {
    const float4* x4 = (const float4*)d_in[0];
    const float*  wT = (const float*)d_in[1];
    const float*  wH = (const float*)d_in[2];
    const float*  wW = (const float*)d_in[3];
    cudaFuncSetAttribute(mvf_kernel, cudaFuncAttributeMaxDynamicSharedMemorySize, SMEM_BYTES);
    dim3 grid(Bv, Hv / RR, Tv / TC);   // 8 x 4 x 4 = 128 CTAs
    mvf_kernel<<<grid, NT, SMEM_BYTES>>>(x4, wT, wH, wW, (float4*)d_out);
}